// round 1
// baseline (speedup 1.0000x reference)
#include <cuda_runtime.h>

// Problem constants (fixed by setup_inputs)
#define BB   2
#define HHD  8
#define SEQ  8192
#define DKD  128
#define DVD  128
#define BT   64
#define NCH  128          // SEQ/BT
#define BHT  16           // BB*HHD
#define NCHUNKS 2048      // BHT*NCH
#define OSZ  16777216     // BHT*SEQ*DVD  (size of o)

#define P1_SMEM ((128*68*2 + 64*68 + 3*64)*4)
#define P2_SMEM ((128*16 + 64*16 + 3*64*132 + 64*68)*4)

// Scratch (device globals: allocation-free)
__device__ float g_qe[BHT*SEQ*DKD];   // q_norm*scale*eg
__device__ float g_kr[BHT*SEQ*DKD];   // k_norm*eg_last/eg
__device__ float g_w [BHT*SEQ*DKD];   // solved w
__device__ float g_u [BHT*SEQ*DVD];   // solved u
__device__ float g_A [NCHUNKS*BT*BT]; // Aqk (zeros above diag)
__device__ float g_egl[NCHUNKS];      // eg at last row of chunk

// ---------------------------------------------------------------------------
// Phase 1: per-chunk (2048 CTAs). Normalize, cumsum gates, A0/Aqk matmuls,
// unit-lower triangular solve for w,u. All fp32.
// ---------------------------------------------------------------------------
__global__ void __launch_bounds__(256) p1_kernel(
    const float* __restrict__ q, const float* __restrict__ k,
    const float* __restrict__ v, const float* __restrict__ g,
    const float* __restrict__ beta)
{
    extern __shared__ float sm[];
    float* skT = sm;                 // [128][68] k transposed (normalized)
    float* sqT = skT + 128*68;       // [128][68] q transposed (normalized*scale)
    float* sA0 = sqT + 128*68;       // [64][68]  strictly-lower A0
    float* seg = sA0 + 64*68;        // [64] exp(cumsum g)
    float* sie = seg + 64;           // [64] 1/seg
    float* sb  = sie + 64;           // [64] beta
    __shared__ float sgr[BT];

    const int cid = blockIdx.x;
    const int bh  = cid / NCH, n = cid % NCH;
    const int rowbase = bh*SEQ + n*BT;
    const int t = threadIdx.x;
    const int lane = t & 31, wid = t >> 5;

    if (t < BT) { sb[t] = beta[rowbase + t]; sgr[t] = g[rowbase + t]; }
    __syncthreads();
    if (t == 0) {
        float run = 0.f;
        for (int i = 0; i < BT; i++) {
            run += sgr[i];
            float e = expf(run);
            seg[i] = e; sie[i] = 1.f / e;
        }
        g_egl[cid] = seg[BT-1];
    }
    // normalize rows of q,k; store transposed
    for (int r = wid; r < BT; r += 8) {
        const float* kp = k + (size_t)(rowbase + r)*DKD;
        const float* qp = q + (size_t)(rowbase + r)*DKD;
        float k0=kp[lane],k1=kp[lane+32],k2=kp[lane+64],k3=kp[lane+96];
        float q0=qp[lane],q1=qp[lane+32],q2=qp[lane+64],q3=qp[lane+96];
        float ssk = k0*k0+k1*k1+k2*k2+k3*k3;
        float ssq = q0*q0+q1*q1+q2*q2+q3*q3;
        #pragma unroll
        for (int o = 16; o; o >>= 1) {
            ssk += __shfl_xor_sync(0xffffffffu, ssk, o);
            ssq += __shfl_xor_sync(0xffffffffu, ssq, o);
        }
        float ik = 1.f/(sqrtf(ssk)+1e-6f);
        float iq = 0.08838834764831845f/(sqrtf(ssq)+1e-6f);  // scale=K^-0.5 folded in
        skT[(lane    )*68+r]=k0*ik; skT[(lane+32)*68+r]=k1*ik;
        skT[(lane+64)*68+r]=k2*ik; skT[(lane+96)*68+r]=k3*ik;
        sqT[(lane    )*68+r]=q0*iq; sqT[(lane+32)*68+r]=q1*iq;
        sqT[(lane+64)*68+r]=q2*iq; sqT[(lane+96)*68+r]=q3*iq;
    }
    __syncthreads();

    // Fused A0 (k·k^T) + Aqk (q·k^T): 4x4 register tiles on a 16x16 thread grid
    const int ty4 = (t >> 4)*4, tx4 = (t & 15)*4;
    float aK[16], aQ[16];
    #pragma unroll
    for (int z = 0; z < 16; z++) { aK[z] = 0.f; aQ[z] = 0.f; }
    #pragma unroll 4
    for (int kk = 0; kk < DKD; kk++) {
        const float* rk = skT + kk*68;
        float4 b4  = *(const float4*)(rk + tx4);
        float4 ak4 = *(const float4*)(rk + ty4);
        float4 aq4 = *(const float4*)(sqT + kk*68 + ty4);
        float bv[4] = {b4.x,b4.y,b4.z,b4.w};
        float kv[4] = {ak4.x,ak4.y,ak4.z,ak4.w};
        float qv[4] = {aq4.x,aq4.y,aq4.z,aq4.w};
        #pragma unroll
        for (int ii = 0; ii < 4; ii++)
            #pragma unroll
            for (int jj = 0; jj < 4; jj++) {
                aK[ii*4+jj] += kv[ii]*bv[jj];
                aQ[ii*4+jj] += qv[ii]*bv[jj];
            }
    }
    #pragma unroll
    for (int ii = 0; ii < 4; ii++) {
        int i = ty4 + ii;
        float segi = seg[i], bi = sb[i];
        #pragma unroll
        for (int jj = 0; jj < 4; jj++) {
            int j = tx4 + jj;
            float rat = segi * sie[j];        // exp(gc_i - gc_j)
            if (j < i) sA0[i*68+j] = aK[ii*4+jj]*rat*bi;
            float f = (j < i) ? rat : ((j == i) ? 1.f : 0.f);
            g_A[(size_t)cid*4096 + i*64 + j] = aQ[ii*4+jj]*f;
        }
    }
    __syncthreads();

    // Emit qe = q*scale*eg and kr = k_norm * eg_last/eg
    {
        int c = t & 127, hb = t >> 7;
        float egl = seg[BT-1];
        for (int i = hb*32; i < hb*32 + 32; i++) {
            g_qe[(size_t)(rowbase+i)*DKD + c] = sqT[c*68+i]*seg[i];
            g_kr[(size_t)(rowbase+i)*DKD + c] = skT[c*68+i]*(egl*sie[i]);
        }
    }

    // Unit-lower triangular solve, one rhs column per thread, column in regs.
    // rhs = [beta*k_norm*eg | beta*v]  (256 columns)
    float x[64];
    if (t < 128) {
        #pragma unroll
        for (int i = 0; i < 64; i++) x[i] = sb[i]*skT[t*68+i]*seg[i];
    } else {
        const float* vp = v + (size_t)rowbase*DVD + (t - 128);
        #pragma unroll
        for (int i = 0; i < 64; i++) x[i] = sb[i]*vp[i*DVD];
    }
    #pragma unroll
    for (int i = 1; i < 64; i++) {
        float xi = x[i];
        #pragma unroll
        for (int j = 0; j < i; j++) xi -= sA0[i*68+j]*x[j];
        x[i] = xi;
    }
    if (t < 128) {
        #pragma unroll
        for (int i = 0; i < 64; i++) g_w[(size_t)(rowbase+i)*DKD + t] = x[i];
    } else {
        int c = t - 128;
        #pragma unroll
        for (int i = 0; i < 64; i++) g_u[(size_t)(rowbase+i)*DVD + c] = x[i];
    }
}

// ---------------------------------------------------------------------------
// Phase 2: state recurrence. 128 CTAs = 16 (b,h) x 8 V-slices of width 16.
// State slice S[128][16] lives in smem across all 128 chunk steps.
// ---------------------------------------------------------------------------
__global__ void __launch_bounds__(256) p2_kernel(float* __restrict__ out, int write_sf)
{
    extern __shared__ float sm[];
    float* sS  = sm;              // [128][16] state slice
    float* svn = sS  + 128*16;    // [64][16]  v_new
    float* sw  = svn + 64*16;     // [64][132]
    float* sqe = sw  + 64*132;    // [64][132]
    float* skr = sqe + 64*132;    // [64][132]
    float* sA  = skr + 64*132;    // [64][68]

    const int t  = threadIdx.x;
    const int bh = blockIdx.x >> 3;
    const int vb = (blockIdx.x & 7) * 16;

    for (int i = t; i < 128*16; i += 256) sS[i] = 0.f;

    const int r   = t >> 2, cq = t & 3;   // mapping for v_new / o
    const int kk2 = t >> 1, ch = t & 1;   // mapping for S update

    for (int n = 0; n < NCH; n++) {
        __syncthreads();
        const size_t rb = (size_t)bh*SEQ + (size_t)n*BT;   // row index
        const float4* wg = (const float4*)(g_w  + rb*DKD);
        const float4* qg = (const float4*)(g_qe + rb*DKD);
        const float4* kg = (const float4*)(g_kr + rb*DKD);
        #pragma unroll
        for (int it = 0; it < 8; it++) {
            int idx = t + 256*it;            // float4 index 0..2047
            int row = idx >> 5, col = (idx & 31)*4;
            *(float4*)&sw [row*132+col] = wg[idx];
            *(float4*)&sqe[row*132+col] = qg[idx];
            *(float4*)&skr[row*132+col] = kg[idx];
        }
        const float4* Ag = (const float4*)(g_A + (size_t)(bh*NCH + n)*4096);
        #pragma unroll
        for (int it = 0; it < 4; it++) {
            int idx = t + 256*it;            // 0..1023
            int row = idx >> 4, col = (idx & 15)*4;
            *(float4*)&sA[row*68+col] = Ag[idx];
        }
        const float egl = g_egl[bh*NCH + n];
        __syncthreads();

        // v_new = u - w @ S ; o_inter = qe @ S   (fused pass over S)
        float4 uu = *(const float4*)(g_u + (rb + r)*DVD + vb + cq*4);
        float vx=uu.x, vy=uu.y, vz=uu.z, vw=uu.w;
        float ox=0.f, oy=0.f, oz=0.f, ow=0.f;
        #pragma unroll 8
        for (int kk = 0; kk < DKD; kk++) {
            float aw = sw [r*132+kk];
            float aq = sqe[r*132+kk];
            float4 s = *(const float4*)&sS[kk*16 + cq*4];
            vx -= aw*s.x; vy -= aw*s.y; vz -= aw*s.z; vw -= aw*s.w;
            ox += aq*s.x; oy += aq*s.y; oz += aq*s.z; ow += aq*s.w;
        }
        *(float4*)&svn[r*16 + cq*4] = make_float4(vx,vy,vz,vw);
        __syncthreads();

        // o_intra = Aqk @ v_new (Aqk has zeros above diag)
        #pragma unroll 8
        for (int j = 0; j < 64; j++) {
            float a = sA[r*68+j];
            float4 vv = *(const float4*)&svn[j*16 + cq*4];
            ox += a*vv.x; oy += a*vv.y; oz += a*vv.z; ow += a*vv.w;
        }
        *(float4*)(out + (rb + r)*DVD + vb + cq*4) = make_float4(ox,oy,oz,ow);

        // S = egl*S + kr^T @ v_new  (each thread owns one S row-half)
        {
            float4 s0 = *(const float4*)&sS[kk2*16 + ch*8];
            float4 s1 = *(const float4*)&sS[kk2*16 + ch*8 + 4];
            float a0=s0.x*egl, a1=s0.y*egl, a2=s0.z*egl, a3=s0.w*egl;
            float b0=s1.x*egl, b1=s1.y*egl, b2=s1.z*egl, b3=s1.w*egl;
            #pragma unroll 8
            for (int r2 = 0; r2 < 64; r2++) {
                float a = skr[r2*132 + kk2];
                float4 v0 = *(const float4*)&svn[r2*16 + ch*8];
                float4 v1 = *(const float4*)&svn[r2*16 + ch*8 + 4];
                a0 += a*v0.x; a1 += a*v0.y; a2 += a*v0.z; a3 += a*v0.w;
                b0 += a*v1.x; b1 += a*v1.y; b2 += a*v1.z; b3 += a*v1.w;
            }
            *(float4*)&sS[kk2*16 + ch*8]     = make_float4(a0,a1,a2,a3);
            *(float4*)&sS[kk2*16 + ch*8 + 4] = make_float4(b0,b1,b2,b3);
        }
    }

    if (write_sf) {
        __syncthreads();
        float4 s0 = *(const float4*)&sS[kk2*16 + ch*8];
        float4 s1 = *(const float4*)&sS[kk2*16 + ch*8 + 4];
        float* dst = out + OSZ + ((size_t)bh*DKD + kk2)*DVD + vb + ch*8;
        *(float4*)dst       = s0;
        *(float4*)(dst + 4) = s1;
    }
}

// ---------------------------------------------------------------------------
extern "C" void kernel_launch(void* const* d_in, const int* in_sizes, int n_in,
                              void* d_out, int out_size)
{
    const float* q    = (const float*)d_in[0];
    const float* k    = (const float*)d_in[1];
    const float* v    = (const float*)d_in[2];
    const float* g    = (const float*)d_in[3];
    const float* beta = (const float*)d_in[4];
    float* out = (float*)d_out;

    cudaFuncSetAttribute(p1_kernel, cudaFuncAttributeMaxDynamicSharedMemorySize, P1_SMEM);
    cudaFuncSetAttribute(p2_kernel, cudaFuncAttributeMaxDynamicSharedMemorySize, P2_SMEM);

    p1_kernel<<<NCHUNKS, 256, P1_SMEM>>>(q, k, v, g, beta);

    int wsf = (out_size > OSZ) ? 1 : 0;
    p2_kernel<<<BHT*8, 256, P2_SMEM>>>(out, wsf);
}

// round 2
// speedup vs baseline: 1.2583x; 1.2583x over previous
#include <cuda_runtime.h>
#include <cstdint>

// Problem constants (fixed by setup_inputs)
#define BB   2
#define HHD  8
#define SEQ  8192
#define DKD  128
#define DVD  128
#define BT   64
#define NCH  128          // SEQ/BT
#define BHT  16           // BB*HHD
#define NCHUNKS 2048      // BHT*NCH
#define OSZ  16777216     // BHT*SEQ*DVD  (size of o)

typedef unsigned long long u64;

// ---- packed f32x2 helpers (FFMA2 path: ptxas never auto-emits, must be PTX) ----
__device__ __forceinline__ u64 pk2(float v) {
    u64 r; asm("mov.b64 %0,{%1,%1};" : "=l"(r) : "f"(v)); return r;
}
__device__ __forceinline__ u64 fma2(u64 a, u64 b, u64 c) {
    u64 d; asm("fma.rn.f32x2 %0,%1,%2,%3;" : "=l"(d) : "l"(a), "l"(b), "l"(c)); return d;
}
__device__ __forceinline__ u64 mul2(u64 a, u64 b) {
    u64 d; asm("mul.rn.f32x2 %0,%1,%2;" : "=l"(d) : "l"(a), "l"(b)); return d;
}
__device__ __forceinline__ float2 up2(u64 a) {
    float2 f; asm("mov.b64 {%0,%1},%2;" : "=f"(f.x), "=f"(f.y) : "l"(a)); return f;
}
__device__ __forceinline__ u64 pkab(float a, float b) {
    u64 r; asm("mov.b64 %0,{%1,%2};" : "=l"(r) : "f"(a), "f"(b)); return r;
}

// ---- cp.async helpers ----
__device__ __forceinline__ void cp16(uint32_t dst, const void* src) {
    asm volatile("cp.async.cg.shared.global [%0],[%1],16;" :: "r"(dst), "l"(src));
}
#define CP_COMMIT asm volatile("cp.async.commit_group;")
#define CP_WAIT0  asm volatile("cp.async.wait_group 0;")

// Scratch (device globals: allocation-free)
__device__ float g_qe [BHT*SEQ*DKD];     // q_norm*scale*eg          [row][K]
__device__ float g_krT[NCHUNKS*DKD*BT];  // k_norm*egl/eg transposed [chunk][K][row]
__device__ float g_w  [BHT*SEQ*DKD];     // -solved w                [row][K]
__device__ float g_u  [BHT*SEQ*DVD];     // solved u                 [row][V]
__device__ float g_A  [NCHUNKS*BT*BT];   // Aqk (zeros above diag)
__device__ float g_egl[NCHUNKS];         // eg at last row of chunk

#define P1_SMEM ((128*68*2 + 64*68 + 3*64)*4)
#define P2_SMEM ((64*132*2 + 2*128*68 + 2*64*68 + 2*64*16 + 128*20 + 64*20)*4)

// ---------------------------------------------------------------------------
// Phase 1: per-chunk (2048 CTAs). Normalize, cumsum gates, A0/Aqk matmuls
// (packed f32x2), unit-lower triangular solve (k-col and v-col packed).
// ---------------------------------------------------------------------------
__global__ void __launch_bounds__(256) p1_kernel(
    const float* __restrict__ q, const float* __restrict__ k,
    const float* __restrict__ v, const float* __restrict__ g,
    const float* __restrict__ beta)
{
    extern __shared__ float sm[];
    float* skT = sm;                 // [128][68] k transposed (normalized)
    float* sqT = skT + 128*68;       // [128][68] q transposed (normalized*scale)
    float* sA0 = sqT + 128*68;       // [64][68]  strictly-lower A0
    float* seg = sA0 + 64*68;        // [64] exp(cumsum g)
    float* sie = seg + 64;           // [64] 1/seg
    float* sb  = sie + 64;           // [64] beta
    __shared__ float sgr[BT];

    const int cid = blockIdx.x;
    const int bh  = cid / NCH, n = cid % NCH;
    const int rowbase = bh*SEQ + n*BT;
    const int t = threadIdx.x;
    const int lane = t & 31, wid = t >> 5;

    if (t < BT) { sb[t] = beta[rowbase + t]; sgr[t] = g[rowbase + t]; }
    __syncthreads();
    if (t == 0) {
        float run = 0.f;
        for (int i = 0; i < BT; i++) {
            run += sgr[i];
            float e = expf(run);
            seg[i] = e; sie[i] = 1.f / e;
        }
        g_egl[cid] = seg[BT-1];
    }
    // normalize rows of q,k; store transposed
    for (int r = wid; r < BT; r += 8) {
        const float* kp = k + (size_t)(rowbase + r)*DKD;
        const float* qp = q + (size_t)(rowbase + r)*DKD;
        float k0=kp[lane],k1=kp[lane+32],k2=kp[lane+64],k3=kp[lane+96];
        float q0=qp[lane],q1=qp[lane+32],q2=qp[lane+64],q3=qp[lane+96];
        float ssk = k0*k0+k1*k1+k2*k2+k3*k3;
        float ssq = q0*q0+q1*q1+q2*q2+q3*q3;
        #pragma unroll
        for (int o = 16; o; o >>= 1) {
            ssk += __shfl_xor_sync(0xffffffffu, ssk, o);
            ssq += __shfl_xor_sync(0xffffffffu, ssq, o);
        }
        float ik = 1.f/(sqrtf(ssk)+1e-6f);
        float iq = 0.08838834764831845f/(sqrtf(ssq)+1e-6f);  // scale=K^-0.5 folded in
        skT[(lane    )*68+r]=k0*ik; skT[(lane+32)*68+r]=k1*ik;
        skT[(lane+64)*68+r]=k2*ik; skT[(lane+96)*68+r]=k3*ik;
        sqT[(lane    )*68+r]=q0*iq; sqT[(lane+32)*68+r]=q1*iq;
        sqT[(lane+64)*68+r]=q2*iq; sqT[(lane+96)*68+r]=q3*iq;
    }
    __syncthreads();

    // Fused A0 (k·k^T) + Aqk (q·k^T): 4x4 register tiles, packed f32x2
    const int ty4 = (t >> 4)*4, tx4 = (t & 15)*4;
    u64 aK01[4], aK23[4], aQ01[4], aQ23[4];
    #pragma unroll
    for (int z = 0; z < 4; z++) { aK01[z]=0ull; aK23[z]=0ull; aQ01[z]=0ull; aQ23[z]=0ull; }
    #pragma unroll 4
    for (int kk = 0; kk < DKD; kk++) {
        const float* rk = skT + kk*68;
        ulonglong2 b   = *(const ulonglong2*)(rk + tx4);
        float4 kv4 = *(const float4*)(rk + ty4);
        float4 qv4 = *(const float4*)(sqT + kk*68 + ty4);
        float kvs[4] = {kv4.x,kv4.y,kv4.z,kv4.w};
        float qvs[4] = {qv4.x,qv4.y,qv4.z,qv4.w};
        #pragma unroll
        for (int ii = 0; ii < 4; ii++) {
            u64 kp2 = pk2(kvs[ii]), qp2 = pk2(qvs[ii]);
            aK01[ii] = fma2(kp2, b.x, aK01[ii]);
            aK23[ii] = fma2(kp2, b.y, aK23[ii]);
            aQ01[ii] = fma2(qp2, b.x, aQ01[ii]);
            aQ23[ii] = fma2(qp2, b.y, aQ23[ii]);
        }
    }
    #pragma unroll
    for (int ii = 0; ii < 4; ii++) {
        int i = ty4 + ii;
        float segi = seg[i], bi = sb[i];
        float2 ka = up2(aK01[ii]), kb = up2(aK23[ii]);
        float2 qa = up2(aQ01[ii]), qb = up2(aQ23[ii]);
        float aKv[4] = {ka.x,ka.y,kb.x,kb.y};
        float aQv[4] = {qa.x,qa.y,qb.x,qb.y};
        #pragma unroll
        for (int jj = 0; jj < 4; jj++) {
            int j = tx4 + jj;
            float rat = segi * sie[j];        // exp(gc_i - gc_j)
            if (j < i) sA0[i*68+j] = aKv[jj]*rat*bi;
            float f = (j < i) ? rat : ((j == i) ? 1.f : 0.f);
            g_A[(size_t)cid*4096 + i*64 + j] = aQv[jj]*f;
        }
    }
    __syncthreads();

    // Emit qe = q*scale*eg (row-major)
    {
        int c = t & 127, hb = t >> 7;
        for (int i = hb*32; i < hb*32 + 32; i++)
            g_qe[(size_t)(rowbase+i)*DKD + c] = sqT[c*68+i]*seg[i];
    }
    // Emit krT = k_norm*egl/eg, transposed layout [chunk][K][row]
    {
        int c = t >> 1, half = (t & 1)*32;
        float egl2 = seg[BT-1];
        size_t kb = (size_t)cid*8192 + (size_t)c*64 + half;
        #pragma unroll
        for (int i4 = 0; i4 < 32; i4 += 4) {
            float4 kv = *(const float4*)&skT[c*68 + half + i4];
            float4 iv = *(const float4*)&sie[half + i4];
            float4 o;
            o.x = kv.x*egl2*iv.x; o.y = kv.y*egl2*iv.y;
            o.z = kv.z*egl2*iv.z; o.w = kv.w*egl2*iv.w;
            *(float4*)&g_krT[kb + i4] = o;
        }
    }

    // Unit-lower triangular solve, packed: thread t<128 owns k-col t AND v-col t
    // in the two f32x2 lanes. rhs = [beta*k_norm*eg | beta*v]
    if (t < 128) {
        const float* vp = v + (size_t)rowbase*DVD + t;
        u64 x[64];
        #pragma unroll
        for (int i = 0; i < 64; i++)
            x[i] = pkab(sb[i]*skT[t*68+i]*seg[i], sb[i]*vp[i*DVD]);
        const u64 neg1 = pk2(-1.0f);
        #pragma unroll
        for (int i = 1; i < 64; i++) {
            u64 s0 = 0ull, s1 = 0ull, s2 = 0ull, s3 = 0ull;
            int j = 0;
            #pragma unroll
            for (; j + 4 <= i; j += 4) {
                float4 a4 = *(const float4*)&sA0[i*68+j];
                s0 = fma2(pk2(a4.x), x[j  ], s0);
                s1 = fma2(pk2(a4.y), x[j+1], s1);
                s2 = fma2(pk2(a4.z), x[j+2], s2);
                s3 = fma2(pk2(a4.w), x[j+3], s3);
            }
            #pragma unroll
            for (; j < i; j++) s0 = fma2(pk2(sA0[i*68+j]), x[j], s0);
            u64 ss = fma2(neg1, s1, s0);  // s0 - ... wait: combine then subtract
            // combine positive sums, then x[i] -= sum  (via fma with -1)
            ss = s0;
            ss = fma2(pk2(1.0f), s1, ss);
            ss = fma2(pk2(1.0f), s2, ss);
            ss = fma2(pk2(1.0f), s3, ss);
            x[i] = fma2(neg1, ss, x[i]);
        }
        #pragma unroll
        for (int i = 0; i < 64; i++) {
            float2 xv = up2(x[i]);
            g_w[(size_t)(rowbase+i)*DKD + t] = -xv.x;   // store NEGATED w
            g_u[(size_t)(rowbase+i)*DVD + t] =  xv.y;
        }
    }
}

// ---------------------------------------------------------------------------
// Phase 2: state recurrence. 128 CTAs = 16 (b,h) x 8 V-slices of width 16.
// cp.async pipelined loads; packed f32x2 inner loops.
// ---------------------------------------------------------------------------
__device__ __forceinline__ void p2_prefetch(
    int bh, int n, int buf, int vb, int t,
    uint32_t a_sw, uint32_t a_sqe, uint32_t a_skrT, uint32_t a_sA, uint32_t a_su)
{
    const size_t rb = (size_t)bh*SEQ + (size_t)n*BT;
    const float* wg = g_w   + rb*DKD;
    const float* qg = g_qe  + rb*DKD;
    const float* kg = g_krT + (size_t)(bh*NCH + n)*8192;
    const float* Ag = g_A   + (size_t)(bh*NCH + n)*4096;
    #pragma unroll
    for (int it = 0; it < 8; it++) {
        int idx = t + 256*it;
        int row = idx >> 5, col = (idx & 31)*4;
        cp16(a_sw  + (uint32_t)(row*132+col)*4, wg + idx*4);
        cp16(a_sqe + (uint32_t)(row*132+col)*4, qg + idx*4);
    }
    #pragma unroll
    for (int it = 0; it < 8; it++) {
        int idx = t + 256*it;
        int row = idx >> 4, col = (idx & 15)*4;
        cp16(a_skrT + (uint32_t)buf*(128*68*4) + (uint32_t)(row*68+col)*4, kg + idx*4);
    }
    #pragma unroll
    for (int it = 0; it < 4; it++) {
        int idx = t + 256*it;
        int row = idx >> 4, col = (idx & 15)*4;
        cp16(a_sA + (uint32_t)buf*(64*68*4) + (uint32_t)(row*68+col)*4, Ag + idx*4);
    }
    {
        int row = t >> 2, col = (t & 3)*4;
        cp16(a_su + (uint32_t)buf*(64*16*4) + (uint32_t)t*16,
             g_u + (rb + row)*DVD + vb + col);
    }
}

__global__ void __launch_bounds__(256) p2_kernel(float* __restrict__ out, int write_sf)
{
    extern __shared__ float sm[];
    float* sw   = sm;                   // [64][132]
    float* sqe  = sw   + 64*132;        // [64][132]
    float* skrT = sqe  + 64*132;        // [2][128][68]
    float* sA   = skrT + 2*128*68;      // [2][64][68]
    float* su   = sA   + 2*64*68;       // [2][64][16]
    float* sS   = su   + 2*64*16;       // [128][20] state slice
    float* svn  = sS   + 128*20;        // [64][20]  v_new

    const int t  = threadIdx.x;
    const int bh = blockIdx.x >> 3;
    const int vb = (blockIdx.x & 7) * 16;

    const uint32_t a_sw   = (uint32_t)__cvta_generic_to_shared(sw);
    const uint32_t a_sqe  = (uint32_t)__cvta_generic_to_shared(sqe);
    const uint32_t a_skrT = (uint32_t)__cvta_generic_to_shared(skrT);
    const uint32_t a_sA   = (uint32_t)__cvta_generic_to_shared(sA);
    const uint32_t a_su   = (uint32_t)__cvta_generic_to_shared(su);

    for (int i = t; i < 128*20; i += 256) sS[i] = 0.f;

    p2_prefetch(bh, 0, 0, vb, t, a_sw, a_sqe, a_skrT, a_sA, a_su);
    CP_COMMIT;

    const int r   = t >> 2, cq = t & 3;   // mapping for v_new / o
    const int kk2 = t >> 1, ch = t & 1;   // mapping for S update

    for (int n = 0; n < NCH; n++) {
        const int buf = n & 1;
        CP_WAIT0;
        __syncthreads();

        const size_t rb = (size_t)bh*SEQ + (size_t)n*BT;
        const float egl = g_egl[bh*NCH + n];

        // ---- loop1: v_new = u + (-w)@S ; o_inter = qe@S (fused pass over S)
        ulonglong2 uu = *(const ulonglong2*)&su[buf*1024 + r*16 + cq*4];
        u64 v01 = uu.x, v23 = uu.y, o01 = 0ull, o23 = 0ull;
        const float* swr = sw  + r*132;
        const float* sqr = sqe + r*132;
        #pragma unroll 8
        for (int kk = 0; kk < DKD; kk += 4) {
            float4 w4 = *(const float4*)(swr + kk);
            float4 q4 = *(const float4*)(sqr + kk);
            float ws[4] = {w4.x,w4.y,w4.z,w4.w};
            float qs[4] = {q4.x,q4.y,q4.z,q4.w};
            #pragma unroll
            for (int e = 0; e < 4; e++) {
                ulonglong2 s = *(const ulonglong2*)&sS[(kk+e)*20 + cq*4];
                u64 wp = pk2(ws[e]), qp = pk2(qs[e]);
                v01 = fma2(wp, s.x, v01); v23 = fma2(wp, s.y, v23);
                o01 = fma2(qp, s.x, o01); o23 = fma2(qp, s.y, o23);
            }
        }
        *(ulonglong2*)&svn[r*20 + cq*4] = make_ulonglong2(v01, v23);
        __syncthreads();

        // ---- kick off next chunk's loads (overlaps loops 2+3)
        if (n + 1 < NCH) {
            p2_prefetch(bh, n+1, buf^1, vb, t, a_sw, a_sqe, a_skrT, a_sA, a_su);
            CP_COMMIT;
        }

        // ---- loop2: o += Aqk @ v_new
        const float* sAr = sA + buf*4352 + r*68;
        #pragma unroll 4
        for (int j = 0; j < BT; j += 4) {
            float4 a4 = *(const float4*)(sAr + j);
            float as[4] = {a4.x,a4.y,a4.z,a4.w};
            #pragma unroll
            for (int e = 0; e < 4; e++) {
                ulonglong2 vv = *(const ulonglong2*)&svn[(j+e)*20 + cq*4];
                u64 ap = pk2(as[e]);
                o01 = fma2(ap, vv.x, o01); o23 = fma2(ap, vv.y, o23);
            }
        }
        {
            float2 oa = up2(o01), ob = up2(o23);
            *(float4*)(out + (rb + r)*DVD + vb + cq*4) = make_float4(oa.x, oa.y, ob.x, ob.y);
        }

        // ---- loop3: S = egl*S + kr^T @ v_new (each thread owns 8 S entries)
        {
            const float* skp = skrT + buf*8704 + kk2*68;
            u64 eg2 = pk2(egl);
            ulonglong2 s0 = *(const ulonglong2*)&sS[kk2*20 + ch*8];
            ulonglong2 s1 = *(const ulonglong2*)&sS[kk2*20 + ch*8 + 4];
            u64 a0 = mul2(eg2, s0.x), a1 = mul2(eg2, s0.y);
            u64 a2 = mul2(eg2, s1.x), a3 = mul2(eg2, s1.y);
            #pragma unroll 4
            for (int r2 = 0; r2 < BT; r2 += 4) {
                float4 kr4 = *(const float4*)(skp + r2);
                float ks[4] = {kr4.x,kr4.y,kr4.z,kr4.w};
                #pragma unroll
                for (int e = 0; e < 4; e++) {
                    ulonglong2 va = *(const ulonglong2*)&svn[(r2+e)*20 + ch*8];
                    ulonglong2 vbq = *(const ulonglong2*)&svn[(r2+e)*20 + ch*8 + 4];
                    u64 kp = pk2(ks[e]);
                    a0 = fma2(kp, va.x,  a0); a1 = fma2(kp, va.y,  a1);
                    a2 = fma2(kp, vbq.x, a2); a3 = fma2(kp, vbq.y, a3);
                }
            }
            *(ulonglong2*)&sS[kk2*20 + ch*8]     = make_ulonglong2(a0, a1);
            *(ulonglong2*)&sS[kk2*20 + ch*8 + 4] = make_ulonglong2(a2, a3);
        }
        // next iteration's top barrier orders loop3's sS writes vs loop1 reads
    }

    if (write_sf) {
        __syncthreads();
        ulonglong2 s0 = *(const ulonglong2*)&sS[kk2*20 + ch*8];
        ulonglong2 s1 = *(const ulonglong2*)&sS[kk2*20 + ch*8 + 4];
        float* dst = out + OSZ + ((size_t)bh*DKD + kk2)*DVD + vb + ch*8;
        float2 p0 = up2(s0.x), p1 = up2(s0.y), p2v = up2(s1.x), p3 = up2(s1.y);
        *(float4*)dst       = make_float4(p0.x, p0.y, p1.x, p1.y);
        *(float4*)(dst + 4) = make_float4(p2v.x, p2v.y, p3.x, p3.y);
    }
}

// ---------------------------------------------------------------------------
extern "C" void kernel_launch(void* const* d_in, const int* in_sizes, int n_in,
                              void* d_out, int out_size)
{
    const float* q    = (const float*)d_in[0];
    const float* k    = (const float*)d_in[1];
    const float* v    = (const float*)d_in[2];
    const float* g    = (const float*)d_in[3];
    const float* beta = (const float*)d_in[4];
    float* out = (float*)d_out;

    cudaFuncSetAttribute(p1_kernel, cudaFuncAttributeMaxDynamicSharedMemorySize, P1_SMEM);
    cudaFuncSetAttribute(p2_kernel, cudaFuncAttributeMaxDynamicSharedMemorySize, P2_SMEM);

    p1_kernel<<<NCHUNKS, 256, P1_SMEM>>>(q, k, v, g, beta);

    int wsf = (out_size > OSZ) ? 1 : 0;
    p2_kernel<<<BHT*8, 256, P2_SMEM>>>(out, wsf);
}